// round 6
// baseline (speedup 1.0000x reference)
#include <cuda_runtime.h>
#include <cuda_fp16.h>

// Problem constants (fixed by the reference: m = n = 8192, 50 Sinkhorn iters, beta=0.3)
#define MDIM  8192
#define NBLK  152          // GB300 has 152 SMs -> one full wave
#define TPB   256
#define NITER 50
#define BETA  0.3f

// ---- scratch (device globals: no allocation allowed in kernel_launch) ----
static __device__ __half g_sh[(size_t)MDIM * MDIM];     // fp16 copy of scores (128 MB)
static __device__ float  g_v[MDIM];                     // Sinkhorn v
static __device__ float  g_u[MDIM];                     // Sinkhorn u (last iteration's)
static __device__ float  g_part[(size_t)NBLK * MDIM];   // per-block column partial sums
static __device__ float  g_losspart[NBLK];              // per-block loss partials

__device__ __forceinline__ float warp_sum(float v) {
#pragma unroll
    for (int o = 16; o; o >>= 1) v += __shfl_xor_sync(0xffffffffu, v, o);
    return v;
}
__device__ __forceinline__ float warp_max(float v) {
#pragma unroll
    for (int o = 16; o; o >>= 1) v = fmaxf(v, __shfl_xor_sync(0xffffffffu, v, o));
    return v;
}

// v <- 0
__global__ void k_init_v() {
    int j = blockIdx.x * blockDim.x + threadIdx.x;
    if (j < MDIM) g_v[j] = 0.f;
}

// fp32 -> fp16 copy (one pass; iterations then read half the bytes)
__global__ void k_convert(const float* __restrict__ in) {
    size_t i = (size_t)blockIdx.x * blockDim.x + threadIdx.x;   // float4 index
    float4 f = reinterpret_cast<const float4*>(in)[i];
    union { uint2 u; __half2 h[2]; } P;
    P.h[0] = __floats2half2_rn(f.x, f.y);
    P.h[1] = __floats2half2_rn(f.z, f.w);
    reinterpret_cast<uint2*>(g_sh)[i] = P.u;
}

// One fused Sinkhorn iteration body: for each row, u_i = log_mu - LSE_j(s_ij + v_j),
// and accumulate column partials  P[b][j] = sum_{i in block} exp(s_ij + u_i).
// Thread t owns columns {g*2048 + 8t .. +7 : g=0..3}; column accumulators live in registers.
// Depth-2 row prefetch (8 LDG.128 in flight/thread = 32KB/SM) + parity-buffered smem
// reduction (ONE __syncthreads per row).
__global__ void __launch_bounds__(TPB, 1) k_iter() {
    const int tid = threadIdx.x;
    const int b   = blockIdx.x;
    const int r0  = (b * MDIM) / NBLK;
    const int r1  = ((b + 1) * MDIM) / NBLK;
    const float L2E    = 1.4426950408889634f;
    const float LOG_MU = -9.704060527839234f;   // log(1/(m+n)) = -log(16384)
    const float MUc    = 6.103515625e-5f;       // 1/16384

    float vl2e[4][8];   // v_j * log2(e) for my 32 columns (constant over rows)
    float cacc[4][8];   // column accumulators (exp(-v_j) applied at writeout)
#pragma unroll
    for (int g = 0; g < 4; g++) {
        int cb = (g << 11) + (tid << 3);
        float4 a = *reinterpret_cast<const float4*>(g_v + cb);
        float4 c = *reinterpret_cast<const float4*>(g_v + cb + 4);
        vl2e[g][0] = a.x * L2E; vl2e[g][1] = a.y * L2E;
        vl2e[g][2] = a.z * L2E; vl2e[g][3] = a.w * L2E;
        vl2e[g][4] = c.x * L2E; vl2e[g][5] = c.y * L2E;
        vl2e[g][6] = c.z * L2E; vl2e[g][7] = c.w * L2E;
#pragma unroll
        for (int k = 0; k < 8; k++) cacc[g][k] = 0.f;
    }

    __shared__ float sred[2][8];   // parity double-buffer -> one sync per row

    // depth-2 software pipeline (every block has >= 53 rows)
    uint4 raw[2][4];
    {
        const uint4* rA = reinterpret_cast<const uint4*>(g_sh + (size_t)r0 * MDIM);
        const uint4* rB = reinterpret_cast<const uint4*>(g_sh + (size_t)(r0 + 1) * MDIM);
#pragma unroll
        for (int g = 0; g < 4; g++) { raw[0][g] = rA[(g << 8) + tid]; raw[1][g] = rB[(g << 8) + tid]; }
    }

    for (int r = r0; r < r1; r++) {
        const int p = (r - r0) & 1;
        uint4 cur[4];
#pragma unroll
        for (int g = 0; g < 4; g++) cur[g] = raw[p][g];
        if (r + 2 < r1) {
            const uint4* row = reinterpret_cast<const uint4*>(g_sh + (size_t)(r + 2) * MDIM);
#pragma unroll
            for (int g = 0; g < 4; g++) raw[p][g] = row[(g << 8) + tid];
        }

        // e_k = exp(s + v_k)   (no max-shift needed in this gauge: |s+v| < ~10, fp32-safe)
        float e[4][8];
        float lsum = 0.f;
#pragma unroll
        for (int g = 0; g < 4; g++) {
            union { uint4 u; __half2 h[4]; } P; P.u = cur[g];
#pragma unroll
            for (int q = 0; q < 4; q++) {
                float2 f = __half22float2(P.h[q]);
                float e0 = exp2f(fmaf(f.x, L2E, vl2e[g][2 * q]));
                float e1 = exp2f(fmaf(f.y, L2E, vl2e[g][2 * q + 1]));
                e[g][2 * q]     = e0;
                e[g][2 * q + 1] = e1;
                lsum += e0 + e1;
            }
        }

        float ws = warp_sum(lsum);
        if ((tid & 31) == 0) sred[p][tid >> 5] = ws;
        __syncthreads();                            // single sync: parity protects reuse
        float S = 0.f;
#pragma unroll
        for (int w = 0; w < 8; w++) S += sred[p][w];   // fixed order -> deterministic

        if (tid == 0) g_u[r] = LOG_MU - __logf(S);

        // exp(s+u) = e_k * (mu/S) * exp(-v_k); exp(-v_k) is per-column -> applied at writeout
        float rs = MUc / S;
#pragma unroll
        for (int g = 0; g < 4; g++)
#pragma unroll
            for (int k = 0; k < 8; k++)
                cacc[g][k] = fmaf(e[g][k], rs, cacc[g][k]);
    }

    float* outp = g_part + (size_t)b * MDIM;
#pragma unroll
    for (int g = 0; g < 4; g++) {
        int cb = (g << 11) + (tid << 3);
        float4 o0, o1;
        o0.x = cacc[g][0] * exp2f(-vl2e[g][0]);
        o0.y = cacc[g][1] * exp2f(-vl2e[g][1]);
        o0.z = cacc[g][2] * exp2f(-vl2e[g][2]);
        o0.w = cacc[g][3] * exp2f(-vl2e[g][3]);
        o1.x = cacc[g][4] * exp2f(-vl2e[g][4]);
        o1.y = cacc[g][5] * exp2f(-vl2e[g][5]);
        o1.z = cacc[g][6] * exp2f(-vl2e[g][6]);
        o1.w = cacc[g][7] * exp2f(-vl2e[g][7]);
        *reinterpret_cast<float4*>(outp + cb)     = o0;
        *reinterpret_cast<float4*>(outp + cb + 4) = o1;
    }
}

// v_j = log_nu - log( sum_b P[b][j] )
// 128 CTAs; block owns 64 columns; the 152 partial rows are split 4-ways across
// thread groups (38 fully-unrolled independent loads/thread -> deep MLP), smem finish.
__global__ void __launch_bounds__(TPB, 1) k_colreduce() {
    const float LOG_MU = -9.704060527839234f;   // log_nu == log_mu
    const int c   = (blockIdx.x << 6) + (threadIdx.x & 63);
    const int grp = threadIdx.x >> 6;           // 0..3, each sums 38 of 152 rows
    float s = 0.f;
#pragma unroll
    for (int k = 0; k < 38; k++)
        s += g_part[(size_t)(grp * 38 + k) * MDIM + c];

    __shared__ float sd[TPB];
    sd[threadIdx.x] = s;
    __syncthreads();
    if (grp == 0) {
        float t = sd[threadIdx.x] + sd[threadIdx.x + 64]
                + sd[threadIdx.x + 128] + sd[threadIdx.x + 192];  // fixed order
        g_v[c] = LOG_MU - __logf(t);
    }
}

// Final loss pass over the fp32 matrix (depth-1 row prefetch):
//  lp = scale*s - L_i,  L_i = LSE_j(scale*s)  (max-shifted; scale=100 demands fp32 input)
//  Q_ij = base_ij * rowq,  base = exp(s+v), rowq = exp(u + log(m+n))
//  per_row = beta*(L*SumQ - scale*Sum(s*Q)) + (1-beta)*(L - scale*s_ii)
__global__ void __launch_bounds__(TPB, 1) k_final(const float* __restrict__ Sm,
                                                  const float* __restrict__ scale_p) {
    const int tid = threadIdx.x;
    const int b   = blockIdx.x;
    const int r0  = (b * MDIM) / NBLK;
    const int r1  = ((b + 1) * MDIM) / NBLK;
    const float L2E    = 1.4426950408889634f;
    const float LOG_MU = -9.704060527839234f;
    const float scale  = *scale_p;
    const float sL2E   = scale * L2E;

    float vl2e[4][8];
#pragma unroll
    for (int g = 0; g < 4; g++) {
        int cb = (g << 11) + (tid << 3);
        float4 a = *reinterpret_cast<const float4*>(g_v + cb);
        float4 c = *reinterpret_cast<const float4*>(g_v + cb + 4);
        vl2e[g][0] = a.x * L2E; vl2e[g][1] = a.y * L2E;
        vl2e[g][2] = a.z * L2E; vl2e[g][3] = a.w * L2E;
        vl2e[g][4] = c.x * L2E; vl2e[g][5] = c.y * L2E;
        vl2e[g][6] = c.z * L2E; vl2e[g][7] = c.w * L2E;
    }

    __shared__ float smax[2][8], sA[2][8], sB[2][8], sC[2][8];
    __shared__ float sdiag[2];
    float rowloss = 0.f;

    // depth-1 prefetch
    float4 nxt[8];
    {
        const float4* row = reinterpret_cast<const float4*>(Sm + (size_t)r0 * MDIM);
#pragma unroll
        for (int g = 0; g < 4; g++) {
            nxt[2 * g]     = row[(g << 9) + (tid << 1)];
            nxt[2 * g + 1] = row[(g << 9) + (tid << 1) + 1];
        }
    }

    for (int r = r0; r < r1; r++) {
        const int p = (r - r0) & 1;
        float val[4][8];
#pragma unroll
        for (int g = 0; g < 4; g++) {
            float4 a = nxt[2 * g], c = nxt[2 * g + 1];
            val[g][0] = a.x; val[g][1] = a.y; val[g][2] = a.z; val[g][3] = a.w;
            val[g][4] = c.x; val[g][5] = c.y; val[g][6] = c.z; val[g][7] = c.w;
        }
        if (r + 1 < r1) {
            const float4* row = reinterpret_cast<const float4*>(Sm + (size_t)(r + 1) * MDIM);
#pragma unroll
            for (int g = 0; g < 4; g++) {
                nxt[2 * g]     = row[(g << 9) + (tid << 1)];
                nxt[2 * g + 1] = row[(g << 9) + (tid << 1) + 1];
            }
        }

        float m = val[0][0];
#pragma unroll
        for (int g = 0; g < 4; g++)
#pragma unroll
            for (int k = 0; k < 8; k++) m = fmaxf(m, val[g][k]);
        m = warp_max(m);

        if (tid == ((r >> 3) & 255)) sdiag[p] = val[r >> 11][r & 7];  // owner of column r
        if ((tid & 31) == 0) smax[p][tid >> 5] = m;
        __syncthreads();
        float M = smax[p][0];
#pragma unroll
        for (int w = 1; w < 8; w++) M = fmaxf(M, smax[p][w]);

        float negML = -M * sL2E;
        float aE = 0.f, aB = 0.f, aSB = 0.f;
#pragma unroll
        for (int g = 0; g < 4; g++)
#pragma unroll
            for (int k = 0; k < 8; k++) {
                float s = val[g][k];
                aE += exp2f(fmaf(s, sL2E, negML));                 // exp(scale*(s-M))
                float base = exp2f(fmaf(s, L2E, vl2e[g][k]));      // exp(s+v)
                aB += base;
                aSB = fmaf(s, base, aSB);
            }
        aE = warp_sum(aE); aB = warp_sum(aB); aSB = warp_sum(aSB);
        if ((tid & 31) == 0) { int w = tid >> 5; sA[p][w] = aE; sB[p][w] = aB; sC[p][w] = aSB; }
        __syncthreads();

        if (tid == 0) {
            float SE = 0.f, SBv = 0.f, SSv = 0.f;
#pragma unroll
            for (int w = 0; w < 8; w++) { SE += sA[p][w]; SBv += sB[p][w]; SSv += sC[p][w]; }
            float L    = fmaf(scale, M, __logf(SE));
            float rowq = exp2f((g_u[r] - LOG_MU) * L2E);   // exp(u + log(m+n))
            rowloss += BETA * (L * (SBv * rowq) - scale * (SSv * rowq))
                     + (1.f - BETA) * (L - scale * sdiag[p]);
        }
    }
    if (tid == 0) g_losspart[b] = rowloss;
}

// final scalar: mean over rows (fixed-order reduction -> deterministic)
__global__ void k_loss(float* __restrict__ out) {
    int tid = threadIdx.x;
    float v = (tid < NBLK) ? g_losspart[tid] : 0.f;
    v = warp_sum(v);
    __shared__ float sred[8];
    if ((tid & 31) == 0) sred[tid >> 5] = v;
    __syncthreads();
    if (tid == 0) {
        float t = 0.f;
#pragma unroll
        for (int w = 0; w < 8; w++) t += sred[w];
        out[0] = t / (float)MDIM;
    }
}

extern "C" void kernel_launch(void* const* d_in, const int* in_sizes, int n_in,
                              void* d_out, int out_size) {
    (void)in_sizes; (void)n_in; (void)out_size;
    const float* Sm    = (const float*)d_in[0];   // similarity_matrix [8192,8192] f32
    const float* scale = (const float*)d_in[1];   // logit_scale scalar f32
    float* out = (float*)d_out;

    k_init_v<<<MDIM / TPB, TPB>>>();
    k_convert<<<(int)(((size_t)MDIM * MDIM / 4) / TPB), TPB>>>(Sm);

    for (int it = 0; it < NITER; it++) {
        k_iter<<<NBLK, TPB>>>();
        k_colreduce<<<MDIM / (TPB / 4), TPB>>>();   // 128 CTAs x 256 thr
    }

    k_final<<<NBLK, TPB>>>(Sm, scale);
    k_loss<<<1, TPB>>>(out);
}

// round 7
// speedup vs baseline: 1.1857x; 1.1857x over previous
#include <cuda_runtime.h>
#include <cuda_fp16.h>

// Problem constants (fixed by the reference: m = n = 8192, 50 Sinkhorn iters, beta=0.3)
#define MDIM  8192
#define NBLK  148          // <= SM count (B300:148, GB300:152) -> one resident wave at occ 1
#define TPB   256
#define NITER 50
#define BETA  0.3f

// ---- scratch (device globals: no allocation allowed in kernel_launch) ----
static __device__ __half g_sh[(size_t)MDIM * MDIM];     // fp16 copy of scores (128 MB)
static __device__ float  g_v[MDIM];                     // Sinkhorn v
static __device__ float  g_u[MDIM];                     // Sinkhorn u (last iteration's)
static __device__ float  g_part[(size_t)NBLK * MDIM];   // per-block column partial sums
static __device__ float  g_losspart[NBLK];              // per-block loss partials
static __device__ unsigned g_cnt;                       // grid-barrier arrive counter
static __device__ unsigned g_gen;                       // grid-barrier generation

__device__ __forceinline__ float warp_sum(float v) {
#pragma unroll
    for (int o = 16; o; o >>= 1) v += __shfl_xor_sync(0xffffffffu, v, o);
    return v;
}
__device__ __forceinline__ float warp_max(float v) {
#pragma unroll
    for (int o = 16; o; o >>= 1) v = fmaxf(v, __shfl_xor_sync(0xffffffffu, v, o));
    return v;
}

// Device-wide barrier: all NBLK CTAs resident (one wave, occ 1). Deterministic.
__device__ __forceinline__ void grid_bar(unsigned want) {
    __syncthreads();
    if (threadIdx.x == 0) {
        __threadfence();
        unsigned a = atomicAdd(&g_cnt, 1u);
        if (a == NBLK - 1u) {
            atomicExch(&g_cnt, 0u);
            __threadfence();
            atomicExch(&g_gen, want);           // release
        } else {
            while (*((volatile unsigned*)&g_gen) < want) __nanosleep(64);
        }
        __threadfence();                         // acquire
    }
    __syncthreads();
}

// barrier state reset (runs once per graph replay)
__global__ void k_init() {
    if (threadIdx.x == 0 && blockIdx.x == 0) { g_cnt = 0u; g_gen = 0u; }
}

// fp32 -> fp16 copy (one pass; iterations then read half the bytes)
__global__ void k_convert(const float* __restrict__ in) {
    size_t i = (size_t)blockIdx.x * blockDim.x + threadIdx.x;   // float4 index
    float4 f = reinterpret_cast<const float4*>(in)[i];
    union { uint2 u; __half2 h[2]; } P;
    P.h[0] = __floats2half2_rn(f.x, f.y);
    P.h[1] = __floats2half2_rn(f.z, f.w);
    reinterpret_cast<uint2*>(g_sh)[i] = P.u;
}

// Persistent fused Sinkhorn: 50 iterations, grid-barrier between row phase and
// column reduce. Thread t owns columns {g*2048 + 8t .. +7 : g=0..3}; column
// accumulators live in registers. Row loop = verified round-5 structure
// (depth-1 prefetch, two syncs per row).
__global__ void __launch_bounds__(TPB, 1) k_sinkhorn() {
    const int tid = threadIdx.x;
    const int b   = blockIdx.x;
    const int r0  = (b * MDIM) / NBLK;
    const int r1  = ((b + 1) * MDIM) / NBLK;
    const float L2E    = 1.4426950408889634f;
    const float LOG_MU = -9.704060527839234f;   // log(1/(m+n)) = -log(16384)
    const float MUc    = 6.103515625e-5f;       // 1/16384

    // column-reduce ownership: block b owns columns [c0, c1); 4 thread-groups
    // of 64 lanes each sum 37 of the 148 partial rows.
    const int c0 = (b * MDIM) / NBLK;
    const int c1 = ((b + 1) * MDIM) / NBLK;
    const int nc = c1 - c0;
    const int cl = tid & 63;
    const int cg = tid >> 6;

    __shared__ float sred[8];
    __shared__ float csum[4][64];

    float vl2e[4][8];   // v_j * log2(e) for my 32 columns (v = 0 at iteration 1)
#pragma unroll
    for (int g = 0; g < 4; g++)
#pragma unroll
        for (int k = 0; k < 8; k++) vl2e[g][k] = 0.f;

    // prefetch first row
    uint4 raw[4];
    {
        const uint4* row = reinterpret_cast<const uint4*>(g_sh + (size_t)r0 * MDIM);
#pragma unroll
        for (int g = 0; g < 4; g++) raw[g] = row[(g << 8) + tid];
    }

    unsigned gen = 0;

    for (int it = 0; it < NITER; it++) {
        // ---- row phase: u_i = log_mu - LSE_j(s_ij + v_j); accumulate col partials ----
        float cacc[4][8];
#pragma unroll
        for (int g = 0; g < 4; g++)
#pragma unroll
            for (int k = 0; k < 8; k++) cacc[g][k] = 0.f;

        for (int r = r0; r < r1; r++) {
            uint4 cur[4];
#pragma unroll
            for (int g = 0; g < 4; g++) cur[g] = raw[g];
            if (r + 1 < r1) {
                const uint4* row = reinterpret_cast<const uint4*>(g_sh + (size_t)(r + 1) * MDIM);
#pragma unroll
                for (int g = 0; g < 4; g++) raw[g] = row[(g << 8) + tid];
            }

            // e_k = exp(s + v_k)  (no max-shift needed in this gauge: |s+v| < ~10)
            float e[4][8];
            float lsum = 0.f;
#pragma unroll
            for (int g = 0; g < 4; g++) {
                union { uint4 u; __half2 h[4]; } P; P.u = cur[g];
#pragma unroll
                for (int q = 0; q < 4; q++) {
                    float2 f = __half22float2(P.h[q]);
                    float e0 = exp2f(fmaf(f.x, L2E, vl2e[g][2 * q]));
                    float e1 = exp2f(fmaf(f.y, L2E, vl2e[g][2 * q + 1]));
                    e[g][2 * q]     = e0;
                    e[g][2 * q + 1] = e1;
                    lsum += e0 + e1;
                }
            }

            float ws = warp_sum(lsum);
            __syncthreads();                       // guard smem reuse from previous row
            if ((tid & 31) == 0) sred[tid >> 5] = ws;
            __syncthreads();
            float S = 0.f;
#pragma unroll
            for (int w = 0; w < 8; w++) S += sred[w];   // fixed order -> deterministic

            if (tid == 0) g_u[r] = LOG_MU - __logf(S);  // only last iteration's survives

            // exp(s+u) = e_k * (mu/S) * exp(-v_k); exp(-v_k) per-column -> at writeout
            float rs = MUc / S;
#pragma unroll
            for (int g = 0; g < 4; g++)
#pragma unroll
                for (int k = 0; k < 8; k++)
                    cacc[g][k] = fmaf(e[g][k], rs, cacc[g][k]);
        }

        // writeout column partials (apply the per-column exp(-v) factor once)
        {
            float* outp = g_part + (size_t)b * MDIM;
#pragma unroll
            for (int g = 0; g < 4; g++) {
                int cb = (g << 11) + (tid << 3);
                float4 o0, o1;
                o0.x = cacc[g][0] * exp2f(-vl2e[g][0]);
                o0.y = cacc[g][1] * exp2f(-vl2e[g][1]);
                o0.z = cacc[g][2] * exp2f(-vl2e[g][2]);
                o0.w = cacc[g][3] * exp2f(-vl2e[g][3]);
                o1.x = cacc[g][4] * exp2f(-vl2e[g][4]);
                o1.y = cacc[g][5] * exp2f(-vl2e[g][5]);
                o1.z = cacc[g][6] * exp2f(-vl2e[g][6]);
                o1.w = cacc[g][7] * exp2f(-vl2e[g][7]);
                *reinterpret_cast<float4*>(outp + cb)     = o0;
                *reinterpret_cast<float4*>(outp + cb + 4) = o1;
            }
        }

        grid_bar(++gen);    // partials visible everywhere

        // ---- column reduce: v_j = log_nu - log(sum_b P[b][j]) for my columns ----
        {
            float s0 = 0.f, s1 = 0.f, s2 = 0.f, s3 = 0.f;
            if (cl < nc) {
                const float* p = g_part + (size_t)(cg * 37) * MDIM + (c0 + cl);
#pragma unroll
                for (int k = 0; k < 36; k += 4) {
                    s0 += p[(size_t)(k    ) * MDIM];
                    s1 += p[(size_t)(k + 1) * MDIM];
                    s2 += p[(size_t)(k + 2) * MDIM];
                    s3 += p[(size_t)(k + 3) * MDIM];
                }
                s0 += p[(size_t)36 * MDIM];
            }
            csum[cg][cl] = (s0 + s1) + (s2 + s3);
            __syncthreads();
            if (cg == 0 && cl < nc) {
                float t = (csum[0][cl] + csum[1][cl]) + (csum[2][cl] + csum[3][cl]);
                g_v[c0 + cl] = LOG_MU - __logf(t);
            }
        }

        // prefetch next iteration's first row (matrix data independent of v)
        if (it + 1 < NITER) {
            const uint4* row = reinterpret_cast<const uint4*>(g_sh + (size_t)r0 * MDIM);
#pragma unroll
            for (int g = 0; g < 4; g++) raw[g] = row[(g << 8) + tid];
        }

        grid_bar(++gen);    // v visible everywhere

        // reload my 32 v values (L2-hot)
        if (it + 1 < NITER) {
#pragma unroll
            for (int g = 0; g < 4; g++) {
                int cb = (g << 11) + (tid << 3);
                float4 a = *reinterpret_cast<const float4*>(g_v + cb);
                float4 c = *reinterpret_cast<const float4*>(g_v + cb + 4);
                vl2e[g][0] = a.x * L2E; vl2e[g][1] = a.y * L2E;
                vl2e[g][2] = a.z * L2E; vl2e[g][3] = a.w * L2E;
                vl2e[g][4] = c.x * L2E; vl2e[g][5] = c.y * L2E;
                vl2e[g][6] = c.z * L2E; vl2e[g][7] = c.w * L2E;
            }
        }
    }
}

// Final loss pass over the fp32 matrix (depth-1 row prefetch):
//  L_i = LSE_j(scale*s) (max-shifted; scale=100 demands fp32 input)
//  Q_ij = base_ij * rowq, base = exp(s+v), rowq = exp(u + log(m+n))
//  per_row = beta*(L*SumQ - scale*Sum(s*Q)) + (1-beta)*(L - scale*s_ii)
__global__ void __launch_bounds__(TPB, 1) k_final(const float* __restrict__ Sm,
                                                  const float* __restrict__ scale_p) {
    const int tid = threadIdx.x;
    const int b   = blockIdx.x;
    const int r0  = (b * MDIM) / NBLK;
    const int r1  = ((b + 1) * MDIM) / NBLK;
    const float L2E    = 1.4426950408889634f;
    const float LOG_MU = -9.704060527839234f;
    const float scale  = *scale_p;
    const float sL2E   = scale * L2E;

    float vl2e[4][8];
#pragma unroll
    for (int g = 0; g < 4; g++) {
        int cb = (g << 11) + (tid << 3);
        float4 a = *reinterpret_cast<const float4*>(g_v + cb);
        float4 c = *reinterpret_cast<const float4*>(g_v + cb + 4);
        vl2e[g][0] = a.x * L2E; vl2e[g][1] = a.y * L2E;
        vl2e[g][2] = a.z * L2E; vl2e[g][3] = a.w * L2E;
        vl2e[g][4] = c.x * L2E; vl2e[g][5] = c.y * L2E;
        vl2e[g][6] = c.z * L2E; vl2e[g][7] = c.w * L2E;
    }

    __shared__ float smax[2][8], sA[2][8], sB[2][8], sC[2][8];
    __shared__ float sdiag[2];
    float rowloss = 0.f;

    float4 nxt[8];
    {
        const float4* row = reinterpret_cast<const float4*>(Sm + (size_t)r0 * MDIM);
#pragma unroll
        for (int g = 0; g < 4; g++) {
            nxt[2 * g]     = row[(g << 9) + (tid << 1)];
            nxt[2 * g + 1] = row[(g << 9) + (tid << 1) + 1];
        }
    }

    for (int r = r0; r < r1; r++) {
        const int p = (r - r0) & 1;
        float val[4][8];
#pragma unroll
        for (int g = 0; g < 4; g++) {
            float4 a = nxt[2 * g], c = nxt[2 * g + 1];
            val[g][0] = a.x; val[g][1] = a.y; val[g][2] = a.z; val[g][3] = a.w;
            val[g][4] = c.x; val[g][5] = c.y; val[g][6] = c.z; val[g][7] = c.w;
        }
        if (r + 1 < r1) {
            const float4* row = reinterpret_cast<const float4*>(Sm + (size_t)(r + 1) * MDIM);
#pragma unroll
            for (int g = 0; g < 4; g++) {
                nxt[2 * g]     = row[(g << 9) + (tid << 1)];
                nxt[2 * g + 1] = row[(g << 9) + (tid << 1) + 1];
            }
        }

        float m = val[0][0];
#pragma unroll
        for (int g = 0; g < 4; g++)
#pragma unroll
            for (int k = 0; k < 8; k++) m = fmaxf(m, val[g][k]);
        m = warp_max(m);

        if (tid == ((r >> 3) & 255)) sdiag[p] = val[r >> 11][r & 7];  // owner of column r
        if ((tid & 31) == 0) smax[p][tid >> 5] = m;
        __syncthreads();
        float M = smax[p][0];
#pragma unroll
        for (int w = 1; w < 8; w++) M = fmaxf(M, smax[p][w]);

        float negML = -M * sL2E;
        float aE = 0.f, aB = 0.f, aSB = 0.f;
#pragma unroll
        for (int g = 0; g < 4; g++)
#pragma unroll
            for (int k = 0; k < 8; k++) {
                float s = val[g][k];
                aE += exp2f(fmaf(s, sL2E, negML));                 // exp(scale*(s-M))
                float base = exp2f(fmaf(s, L2E, vl2e[g][k]));      // exp(s+v)
                aB += base;
                aSB = fmaf(s, base, aSB);
            }
        aE = warp_sum(aE); aB = warp_sum(aB); aSB = warp_sum(aSB);
        if ((tid & 31) == 0) { int w = tid >> 5; sA[p][w] = aE; sB[p][w] = aB; sC[p][w] = aSB; }
        __syncthreads();

        if (tid == 0) {
            float SE = 0.f, SBv = 0.f, SSv = 0.f;
#pragma unroll
            for (int w = 0; w < 8; w++) { SE += sA[p][w]; SBv += sB[p][w]; SSv += sC[p][w]; }
            float L    = fmaf(scale, M, __logf(SE));
            float rowq = exp2f((g_u[r] - LOG_MU) * L2E);   // exp(u + log(m+n))
            rowloss += BETA * (L * (SBv * rowq) - scale * (SSv * rowq))
                     + (1.f - BETA) * (L - scale * sdiag[p]);
        }
    }
    if (tid == 0) g_losspart[b] = rowloss;
}

// final scalar: mean over rows (fixed-order reduction -> deterministic)
__global__ void k_loss(float* __restrict__ out) {
    int tid = threadIdx.x;
    float v = (tid < NBLK) ? g_losspart[tid] : 0.f;
    v = warp_sum(v);
    __shared__ float sred[8];
    if ((tid & 31) == 0) sred[tid >> 5] = v;
    __syncthreads();
    if (tid == 0) {
        float t = 0.f;
#pragma unroll
        for (int w = 0; w < 8; w++) t += sred[w];
        out[0] = t / (float)MDIM;
    }
}

extern "C" void kernel_launch(void* const* d_in, const int* in_sizes, int n_in,
                              void* d_out, int out_size) {
    (void)in_sizes; (void)n_in; (void)out_size;
    const float* Sm    = (const float*)d_in[0];   // similarity_matrix [8192,8192] f32
    const float* scale = (const float*)d_in[1];   // logit_scale scalar f32
    float* out = (float*)d_out;

    k_init<<<1, 32>>>();
    k_convert<<<(int)(((size_t)MDIM * MDIM / 4) / TPB), TPB>>>(Sm);
    k_sinkhorn<<<NBLK, TPB>>>();
    k_final<<<NBLK, TPB>>>(Sm, scale);
    k_loss<<<1, TPB>>>(out);
}